// round 12
// baseline (speedup 1.0000x reference)
#include <cuda_runtime.h>

#define NMAX 50000
#define EMAX 800000

// ---------------- scratch ----------------
__device__ __align__(16) int   g_ssrc[EMAX];
__device__ __align__(16) int   g_sdst[EMAX];
__device__ __align__(16) int   g_src[EMAX];
__device__ __align__(16) int   g_dst[EMAX];
__device__ __align__(16) int   g_rank[EMAX];
__device__ __align__(16) int   g_hist[NMAX];
__device__ __align__(16) int   g_rowptr[NMAX + 1];
__device__ __align__(16) int   g_bsum[256];
__device__ __align__(16) int   g_boff[256];
__device__ int   g_is64;
__device__ __align__(16) float4 g_edata[EMAX];   // {src, p, wg, -wt} per sorted edge
__device__ __align__(16) float g_vsrc[64];
__device__ __align__(16) float g_vdst[64];
__device__ __align__(16) float g_deg[NMAX];
__device__ __align__(16) float g_dinv[NMAX];
__device__ __align__(16) float g_dinvc[NMAX];
__device__ __align__(16) float g_el[NMAX];
__device__ __align__(16) float g_er[NMAX];
__device__ __align__(16) float g_z[NMAX];
__device__ __align__(16) float g_nsum[NMAX * 64];
__device__ __align__(16) float g_gcnx[NMAX * 64];
__device__ __align__(16) float g_t1[NMAX * 64];
__device__ __align__(16) float g_t2[NMAX * 64];   // stores -prop(T1)
__device__ __align__(16) float g_gatx[NMAX * 64];
__device__ __align__(16) float g_accsage[NMAX * 64];

// ---------------- helpers ----------------
__device__ __forceinline__ float eluf(float v) { return v > 0.f ? v : expm1f(v); }
__device__ __forceinline__ float leakyf(float v) { return v > 0.f ? v : 0.2f * v; }

__device__ __forceinline__ unsigned long long pack2(float lo, float hi) {
    unsigned long long r;
    asm("mov.b64 %0, {%1, %2};" : "=l"(r) : "f"(lo), "f"(hi));
    return r;
}
__device__ __forceinline__ float2 unpack2(unsigned long long v) {
    float lo, hi;
    asm("mov.b64 {%0, %1}, %2;" : "=f"(lo), "=f"(hi) : "l"(v));
    return make_float2(lo, hi);
}
#define FMA2(acc, w, xx) \
    asm("fma.rn.f32x2 %0, %1, %2, %0;" : "+l"(acc) : "l"(w), "l"(xx))
#define ADD2(acc, xx) \
    asm("add.rn.f32x2 %0, %0, %1;" : "+l"(acc) : "l"(xx))

// load 64x64 fp32 matrix into smem (256 threads)
__device__ __forceinline__ void loadW(float* Wsm, const float* __restrict__ Wg, int t) {
    const float4* s = (const float4*)Wg;
    float4* d = (float4*)Wsm;
#pragma unroll
    for (int i = 0; i < 4; i++) d[t + i * 256] = s[t + i * 256];
}

__device__ __forceinline__ void gemv16x2(const float* __restrict__ Wsm,
                                         const float4* __restrict__ Xs,
                                         int tt, int jbase,
                                         unsigned long long acc2[8]) {
#pragma unroll 4
    for (int k4 = 0; k4 < 16; k4++) {
        float4 xq = Xs[k4 * 128 + tt];
#pragma unroll
        for (int s = 0; s < 4; s++) {
            float xv = (s == 0) ? xq.x : (s == 1) ? xq.y : (s == 2) ? xq.z : xq.w;
            unsigned long long xx = pack2(xv, xv);
            const ulonglong2* wp = (const ulonglong2*)(Wsm + (k4 * 4 + s) * 64 + jbase);
            ulonglong2 a = wp[0], b = wp[1], c = wp[2], d = wp[3];
            FMA2(acc2[0], a.x, xx); FMA2(acc2[1], a.y, xx);
            FMA2(acc2[2], b.x, xx); FMA2(acc2[3], b.y, xx);
            FMA2(acc2[4], c.x, xx); FMA2(acc2[5], c.y, xx);
            FMA2(acc2[6], d.x, xx); FMA2(acc2[7], d.y, xx);
        }
    }
}

__device__ __forceinline__ void accInitBias(unsigned long long a[8],
                                            const float* __restrict__ b) {
#pragma unroll
    for (int j = 0; j < 8; j++) a[j] = pack2(b[2 * j], b[2 * j + 1]);
}
__device__ __forceinline__ void accInitZero(unsigned long long a[8]) {
#pragma unroll
    for (int j = 0; j < 8; j++) a[j] = 0ull;
}
__device__ __forceinline__ void accOut(const unsigned long long a[8], float o[16]) {
#pragma unroll
    for (int j = 0; j < 8; j++) {
        float2 p = unpack2(a[j]);
        o[2 * j] = p.x;
        o[2 * j + 1] = p.y;
    }
}

__device__ __forceinline__ void loadXs(float4* Xs, const float4* __restrict__ row,
                                       int tt, int half) {
#pragma unroll
    for (int i = 0; i < 8; i++) {
        int k4 = half * 8 + i;
        Xs[k4 * 128 + tt] = row[k4];
    }
}

// ---------------- CSR build ----------------
__global__ void kinit(const int* __restrict__ raw, int N) {
    int i = blockIdx.x * blockDim.x + threadIdx.x;
    if (i < N) g_hist[i] = 0;
    if (i == 0) {
        int acc = 0;
        for (int k = 0; k < 64; k++) acc |= raw[2 * k + 1];
        g_is64 = (acc == 0) ? 1 : 0;
    }
}

__global__ void kconvert(const void* __restrict__ raw, int E) {
    int is64 = g_is64;
    for (int e = blockIdx.x * blockDim.x + threadIdx.x; e < E;
         e += gridDim.x * blockDim.x) {
        int s, d;
        if (is64) {
            const long long* p = (const long long*)raw;
            s = (int)p[e];
            d = (int)p[(size_t)E + e];
        } else {
            const int* p = (const int*)raw;
            s = p[e];
            d = p[E + e];
        }
        g_src[e] = s;
        g_dst[e] = d;
        g_rank[e] = atomicAdd(&g_hist[d], 1);
    }
}

__global__ void kvec(const float* __restrict__ Wgat,
                     const float* __restrict__ asrc,
                     const float* __restrict__ adst) {
    int k = threadIdx.x;
    if (k < 64) {
        float s1 = 0.f, s2 = 0.f;
        const float* row = Wgat + k * 64;
        for (int j = 0; j < 64; j++) {
            float w = row[j];
            s1 += w * asrc[j];
            s2 += w * adst[j];
        }
        g_vsrc[k] = s1;
        g_vdst[k] = s2;
    }
}

__global__ __launch_bounds__(256) void kbsum(int N) {
    __shared__ int red[256];
    int t = threadIdx.x;
    int i = blockIdx.x * 256 + t;
    red[t] = (i < N) ? g_hist[i] : 0;
    __syncthreads();
    for (int o = 128; o; o >>= 1) {
        if (t < o) red[t] += red[t + o];
        __syncthreads();
    }
    if (t == 0) g_bsum[blockIdx.x] = red[0];
}

__global__ __launch_bounds__(256) void kbscan(int G) {
    __shared__ int s[256];
    int t = threadIdx.x;
    int v = (t < G) ? g_bsum[t] : 0;
    s[t] = v;
    __syncthreads();
    for (int o = 1; o < 256; o <<= 1) {
        int u = (t >= o) ? s[t - o] : 0;
        __syncthreads();
        s[t] += u;
        __syncthreads();
    }
    if (t < G) g_boff[t] = s[t] - v;
}

__global__ __launch_bounds__(256) void kapply(int N, int E) {
    __shared__ int wsum[8];
    int t = threadIdx.x;
    int lane = t & 31, wid = t >> 5;
    int i = blockIdx.x * 256 + t;
    int h = (i < N) ? g_hist[i] : 0;
    int val = h;
#pragma unroll
    for (int o = 1; o < 32; o <<= 1) {
        int u = __shfl_up_sync(0xffffffffu, val, o);
        if (lane >= o) val += u;
    }
    if (lane == 31) wsum[wid] = val;
    __syncthreads();
    if (t < 8) {
        int w = wsum[t];
#pragma unroll
        for (int o = 1; o < 8; o <<= 1) {
            int u = __shfl_up_sync(0xffu, w, o);
            if (t >= o) w += u;
        }
        wsum[t] = w;
    }
    __syncthreads();
    int excl = val - h + (wid ? wsum[wid - 1] : 0) + g_boff[blockIdx.x];
    if (i < N) {
        g_rowptr[i] = excl;
        float deg = (float)h;
        g_deg[i] = deg;
        g_dinv[i] = rsqrtf(deg + 1.f);
        g_dinvc[i] = rsqrtf(fmaxf(deg, 1.f));
    }
    if (i == 0) g_rowptr[N] = E;
}

__global__ void kscatter(int E) {
    int e = blockIdx.x * blockDim.x + threadIdx.x;
    if (e >= E) return;
    int d = g_dst[e];
    int pos = g_rowptr[d] + g_rank[e];
    g_ssrc[pos] = g_src[e];
    g_sdst[pos] = d;
}

// per-sorted-edge weights: {src, p, wg, -wt}
__global__ void kprep(int E) {
    int e = blockIdx.x * blockDim.x + threadIdx.x;
    if (e >= E) return;
    int s = g_ssrc[e];
    int d = g_sdst[e];
    float p = expf(leakyf(g_el[s] + g_er[d]));
    float wg = g_dinv[s] * g_dinv[d];
    float wt = -g_dinvc[s] * g_dinvc[d];
    g_edata[e] = make_float4(__int_as_float(s), p, wg, wt);
}

// ---------------- node kernel 1a: mlp + sage-r GEMVs, el/er dots ------------
__global__ __launch_bounds__(256) void k1a(
    const float* __restrict__ x, const float* __restrict__ wts,
    const float* __restrict__ Wmlp, const float* __restrict__ bmlp,
    const float* __restrict__ Wr, const float* __restrict__ bsage,
    float* __restrict__ out, int N) {
    __shared__ __align__(16) float Wsm[4096];
    __shared__ float4 Xs[2048];
    __shared__ float vs[64], vd[64];
    __shared__ float els[128], ers[128];
    int t = threadIdx.x;
    int tt = t & 127, half = t >> 7;
    int node = blockIdx.x * 128 + tt;
    bool act = node < N;
    if (act) loadXs(Xs, (const float4*)(x + (size_t)node * 64), tt, half);
    if (t < 64) vs[t] = g_vsrc[t];
    else if (t < 128) vd[t - 64] = g_vdst[t - 64];
    loadW(Wsm, Wmlp, t);
    __syncthreads();
    {
        float el = 0.f, er = 0.f;
        if (act) {
#pragma unroll
            for (int i = 0; i < 8; i++) {
                int k4 = half * 8 + i;
                float4 xq = Xs[k4 * 128 + tt];
                el += xq.x * vs[k4 * 4 + 0] + xq.y * vs[k4 * 4 + 1]
                    + xq.z * vs[k4 * 4 + 2] + xq.w * vs[k4 * 4 + 3];
                er += xq.x * vd[k4 * 4 + 0] + xq.y * vd[k4 * 4 + 1]
                    + xq.z * vd[k4 * 4 + 2] + xq.w * vd[k4 * 4 + 3];
            }
        }
        if (half == 1) { els[tt] = el; ers[tt] = er; }
        if (act) {
            float w0 = wts[0];
            float4* o4 = (float4*)(out + (size_t)node * 64);
#pragma unroll
            for (int c = 0; c < 2; c++) {
                int cc = half * 2 + c;
                unsigned long long a2[8];
                accInitBias(a2, bmlp + cc * 16);
                gemv16x2(Wsm, Xs, tt, cc * 16, a2);
                float acc[16];
                accOut(a2, acc);
#pragma unroll
                for (int j = 0; j < 4; j++)
                    o4[cc * 4 + j] = make_float4(w0 * eluf(acc[4 * j + 0]),
                                                 w0 * eluf(acc[4 * j + 1]),
                                                 w0 * eluf(acc[4 * j + 2]),
                                                 w0 * eluf(acc[4 * j + 3]));
            }
        }
        __syncthreads();
        if (half == 0 && act) {
            g_el[node] = el + els[tt];
            g_er[node] = er + ers[tt];
        }
    }
    loadW(Wsm, Wr, t);
    __syncthreads();
    if (act) {
        float4* o4 = (float4*)(g_accsage + (size_t)node * 64);
#pragma unroll
        for (int c = 0; c < 2; c++) {
            int cc = half * 2 + c;
            unsigned long long a2[8];
            accInitBias(a2, bsage + cc * 16);
            gemv16x2(Wsm, Xs, tt, cc * 16, a2);
            float acc[16];
            accOut(a2, acc);
#pragma unroll
            for (int j = 0; j < 4; j++)
                o4[cc * 4 + j] = make_float4(acc[4 * j], acc[4 * j + 1],
                                             acc[4 * j + 2], acc[4 * j + 3]);
        }
    }
}

// ---------------- gather pass A: uniform edge-struct loads, no shuffles -----
__global__ __launch_bounds__(256) void kaggA(const float* __restrict__ x, int N) {
    int gw = (blockIdx.x * 256 + threadIdx.x) >> 5;
    if (gw >= N) return;
    int lane = threadIdx.x & 31;
    int d = gw;
    int beg = g_rowptr[d], end = g_rowptr[d + 1];
    float es = leakyf(g_el[d] + g_er[d]);

    unsigned long long ns = 0ull, gc = 0ull, t1 = 0ull, ga = 0ull;
    float z = expf(es);
#pragma unroll 2
    for (int e = beg; e < end; e++) {
        float4 ed = g_edata[e];                 // warp-uniform broadcast load
        int s = __float_as_int(ed.x);
        float2 xv = ((const float2*)(x + (size_t)s * 64))[lane];
        unsigned long long xx = pack2(xv.x, xv.y);
        ADD2(ns, xx);
        FMA2(gc, pack2(ed.z, ed.z), xx);
        FMA2(t1, pack2(ed.w, ed.w), xx);        // ed.w = -wt
        FMA2(ga, pack2(ed.y, ed.y), xx);
        z += ed.y;                               // identical on all lanes
    }
    float2 v;
    v = unpack2(ns); ((float2*)(g_nsum + (size_t)d * 64))[lane] = v;
    v = unpack2(gc); ((float2*)(g_gcnx + (size_t)d * 64))[lane] = v;
    v = unpack2(t1); ((float2*)(g_t1   + (size_t)d * 64))[lane] = v;
    v = unpack2(ga); ((float2*)(g_gatx + (size_t)d * 64))[lane] = v;
    if (lane == 0) g_z[d] = z;
}

// ---------------- node kernel 1b: sage + gin finalize ----------------
__global__ __launch_bounds__(256) void k1b(const float* __restrict__ x,
                                           const float* __restrict__ wts,
                                           const float* __restrict__ Wl,
                                           const float* __restrict__ Wgin,
                                           const float* __restrict__ bgin,
                                           float* __restrict__ out, int N) {
    __shared__ __align__(16) float Wsm[4096];
    __shared__ float4 Xs[2048];
    int t = threadIdx.x;
    int tt = t & 127, half = t >> 7;
    int node = blockIdx.x * 128 + tt;
    bool act = node < N;
    float invd = 1.f;
    if (act) {
        loadXs(Xs, (const float4*)(g_nsum + (size_t)node * 64), tt, half);
        invd = 1.f / fmaxf(g_deg[node], 1.f);
    }
    loadW(Wsm, Wl, t);
    __syncthreads();
    if (act) {
        float w1 = wts[1];
        float4* o4 = (float4*)(out + (size_t)node * 64);
        const float4* as4 = (const float4*)(g_accsage + (size_t)node * 64);
#pragma unroll
        for (int c = 0; c < 2; c++) {
            int cc = half * 2 + c;
            unsigned long long a2[8];
            accInitZero(a2);
            gemv16x2(Wsm, Xs, tt, cc * 16, a2);
            float acc[16];
            accOut(a2, acc);
#pragma unroll
            for (int j = 0; j < 4; j++) {
                float4 ov = o4[cc * 4 + j];
                float4 as = as4[cc * 4 + j];
                ov.x += w1 * eluf(acc[4 * j + 0] * invd + as.x);
                ov.y += w1 * eluf(acc[4 * j + 1] * invd + as.y);
                ov.z += w1 * eluf(acc[4 * j + 2] * invd + as.z);
                ov.w += w1 * eluf(acc[4 * j + 3] * invd + as.w);
                o4[cc * 4 + j] = ov;
            }
        }
    }
    __syncthreads();
    if (act) {
        const float4* xr = (const float4*)(x + (size_t)node * 64);
#pragma unroll
        for (int i = 0; i < 8; i++) {
            int k4 = half * 8 + i;
            float4 v = Xs[k4 * 128 + tt];
            float4 a = xr[k4];
            Xs[k4 * 128 + tt] = make_float4(v.x + a.x, v.y + a.y, v.z + a.z, v.w + a.w);
        }
    }
    loadW(Wsm, Wgin, t);
    __syncthreads();
    if (act) {
        float w5 = wts[5];
        float4* o4 = (float4*)(out + (size_t)node * 64);
#pragma unroll
        for (int c = 0; c < 2; c++) {
            int cc = half * 2 + c;
            unsigned long long a2[8];
            accInitBias(a2, bgin + cc * 16);
            gemv16x2(Wsm, Xs, tt, cc * 16, a2);
            float acc[16];
            accOut(a2, acc);
#pragma unroll
            for (int j = 0; j < 4; j++) {
                float4 ov = o4[cc * 4 + j];
                ov.x += w5 * eluf(acc[4 * j + 0]);
                ov.y += w5 * eluf(acc[4 * j + 1]);
                ov.z += w5 * eluf(acc[4 * j + 2]);
                ov.w += w5 * eluf(acc[4 * j + 3]);
                o4[cc * 4 + j] = ov;
            }
        }
    }
}

// ---------------- gather pass B: t2' = -prop(T1) via stored -wt -------------
__global__ __launch_bounds__(256) void kaggB(int N) {
    int gw = (blockIdx.x * 256 + threadIdx.x) >> 5;
    if (gw >= N) return;
    int lane = threadIdx.x & 31;
    int d = gw;
    int beg = g_rowptr[d], end = g_rowptr[d + 1];
    unsigned long long t2 = 0ull;
#pragma unroll 2
    for (int e = beg; e < end; e++) {
        float4 ed = g_edata[e];
        int s = __float_as_int(ed.x);
        float2 v = ((const float2*)(g_t1 + (size_t)s * 64))[lane];
        FMA2(t2, pack2(ed.w, ed.w), pack2(v.x, v.y));   // ed.w = -wt
    }
    ((float2*)(g_t2 + (size_t)d * 64))[lane] = unpack2(t2);
}

// ---------------- final node kernel: cheb(3) + gcn + gat -------------------
__global__ __launch_bounds__(256) void kf(const float* __restrict__ x,
                                          const float* __restrict__ wts,
                                          const float* __restrict__ Wcheb,
                                          const float* __restrict__ bcheb,
                                          const float* __restrict__ Wgcn,
                                          const float* __restrict__ bgcn,
                                          const float* __restrict__ Wgat,
                                          const float* __restrict__ bgat,
                                          float* __restrict__ out, int N) {
    __shared__ __align__(16) float Wsm[4096];
    __shared__ float4 Xs[2048];
    int t = threadIdx.x;
    int tt = t & 127, half = t >> 7;
    int node = blockIdx.x * 128 + tt;
    bool act = node < N;
    float res[32];
    if (act) loadXs(Xs, (const float4*)(x + (size_t)node * 64), tt, half);
    loadW(Wsm, Wcheb, t);
    __syncthreads();
    if (act) {
#pragma unroll
        for (int c = 0; c < 2; c++) {
            int cc = half * 2 + c;
            unsigned long long a2[8];
            accInitBias(a2, bcheb + cc * 16);
            gemv16x2(Wsm, Xs, tt, cc * 16, a2);
            accOut(a2, res + c * 16);
        }
    }
    __syncthreads();
    if (act) loadXs(Xs, (const float4*)(g_t1 + (size_t)node * 64), tt, half);
    loadW(Wsm, Wcheb + 4096, t);
    __syncthreads();
    if (act) {
#pragma unroll
        for (int c = 0; c < 2; c++) {
            int cc = half * 2 + c;
            unsigned long long a2[8];
            accInitZero(a2);
            gemv16x2(Wsm, Xs, tt, cc * 16, a2);
            float acc[16];
            accOut(a2, acc);
#pragma unroll
            for (int j = 0; j < 16; j++) res[c * 16 + j] += acc[j];
        }
    }
    __syncthreads();
    // T2 = -2*prop(T1) - x = 2*t2' - x  (t2' = -prop(T1))
    if (act) {
        const float4* xr = (const float4*)(x + (size_t)node * 64);
        const float4* t2r = (const float4*)(g_t2 + (size_t)node * 64);
#pragma unroll
        for (int i = 0; i < 8; i++) {
            int k4 = half * 8 + i;
            float4 a = xr[k4];
            float4 b = t2r[k4];
            Xs[k4 * 128 + tt] = make_float4(2.f * b.x - a.x, 2.f * b.y - a.y,
                                            2.f * b.z - a.z, 2.f * b.w - a.w);
        }
    }
    loadW(Wsm, Wcheb + 8192, t);
    __syncthreads();
    float w2 = wts[2], w3 = wts[3], w4 = wts[4];
    if (act) {
#pragma unroll
        for (int c = 0; c < 2; c++) {
            int cc = half * 2 + c;
            unsigned long long a2[8];
            accInitZero(a2);
            gemv16x2(Wsm, Xs, tt, cc * 16, a2);
            float acc[16];
            accOut(a2, acc);
#pragma unroll
            for (int j = 0; j < 16; j++)
                res[c * 16 + j] = w4 * eluf(res[c * 16 + j] + acc[j]);
        }
    }
    __syncthreads();
    if (act) {
        float dinv = g_dinv[node];
        float di2 = dinv * dinv;
        const float4* xr = (const float4*)(x + (size_t)node * 64);
        const float4* gr = (const float4*)(g_gcnx + (size_t)node * 64);
#pragma unroll
        for (int i = 0; i < 8; i++) {
            int k4 = half * 8 + i;
            float4 a = xr[k4];
            float4 g = gr[k4];
            Xs[k4 * 128 + tt] = make_float4(g.x + di2 * a.x, g.y + di2 * a.y,
                                            g.z + di2 * a.z, g.w + di2 * a.w);
        }
    }
    loadW(Wsm, Wgcn, t);
    __syncthreads();
    if (act) {
#pragma unroll
        for (int c = 0; c < 2; c++) {
            int cc = half * 2 + c;
            unsigned long long a2[8];
            accInitBias(a2, bgcn + cc * 16);
            gemv16x2(Wsm, Xs, tt, cc * 16, a2);
            float acc[16];
            accOut(a2, acc);
#pragma unroll
            for (int j = 0; j < 16; j++) res[c * 16 + j] += w2 * eluf(acc[j]);
        }
    }
    __syncthreads();
    if (act) {
        float es = leakyf(g_el[node] + g_er[node]);
        float cs = expf(es);
        float invz = 1.f / (g_z[node] + 1e-16f);
        const float4* xr = (const float4*)(x + (size_t)node * 64);
        const float4* gr = (const float4*)(g_gatx + (size_t)node * 64);
#pragma unroll
        for (int i = 0; i < 8; i++) {
            int k4 = half * 8 + i;
            float4 a = xr[k4];
            float4 g = gr[k4];
            Xs[k4 * 128 + tt] = make_float4(invz * (g.x + cs * a.x),
                                            invz * (g.y + cs * a.y),
                                            invz * (g.z + cs * a.z),
                                            invz * (g.w + cs * a.w));
        }
    }
    loadW(Wsm, Wgat, t);
    __syncthreads();
    if (act) {
        float4* o4 = (float4*)(out + (size_t)node * 64);
#pragma unroll
        for (int c = 0; c < 2; c++) {
            int cc = half * 2 + c;
            unsigned long long a2[8];
            accInitBias(a2, bgat + cc * 16);
            gemv16x2(Wsm, Xs, tt, cc * 16, a2);
            float acc[16];
            accOut(a2, acc);
#pragma unroll
            for (int j = 0; j < 4; j++) {
                float4 ov = o4[cc * 4 + j];
                ov.x += res[c * 16 + 4 * j + 0] + w3 * eluf(acc[4 * j + 0]);
                ov.y += res[c * 16 + 4 * j + 1] + w3 * eluf(acc[4 * j + 1]);
                ov.z += res[c * 16 + 4 * j + 2] + w3 * eluf(acc[4 * j + 2]);
                ov.w += res[c * 16 + 4 * j + 3] + w3 * eluf(acc[4 * j + 3]);
                o4[cc * 4 + j] = ov;
            }
        }
    }
}

// ---------------- host launcher (graph-capture stream forking) --------------
extern "C" void kernel_launch(void* const* d_in, const int* in_sizes, int n_in,
                              void* d_out, int out_size) {
    static cudaStream_t s1 = nullptr;
    static cudaEvent_t ev_fork = nullptr, ev_a = nullptr, ev_b = nullptr, ev_j = nullptr;
    if (s1 == nullptr) {
        cudaStreamCreateWithFlags(&s1, cudaStreamNonBlocking);
        cudaEventCreateWithFlags(&ev_fork, cudaEventDisableTiming);
        cudaEventCreateWithFlags(&ev_a, cudaEventDisableTiming);
        cudaEventCreateWithFlags(&ev_b, cudaEventDisableTiming);
        cudaEventCreateWithFlags(&ev_j, cudaEventDisableTiming);
    }

    const float* x     = (const float*)d_in[0];
    const float* wts   = (const float*)d_in[1];
    const float* Wmlp  = (const float*)d_in[2];
    const float* bmlp  = (const float*)d_in[3];
    const float* Wl    = (const float*)d_in[4];
    const float* Wr    = (const float*)d_in[5];
    const float* bsage = (const float*)d_in[6];
    const float* Wgcn  = (const float*)d_in[7];
    const float* bgcn  = (const float*)d_in[8];
    const float* Wgat  = (const float*)d_in[9];
    const float* asrc  = (const float*)d_in[10];
    const float* adst  = (const float*)d_in[11];
    const float* bgat  = (const float*)d_in[12];
    const float* Wcheb = (const float*)d_in[13];
    const float* bcheb = (const float*)d_in[14];
    const float* Wgin  = (const float*)d_in[15];
    const float* bgin  = (const float*)d_in[16];
    const void*  eidx  = d_in[17];
    float* out = (float*)d_out;

    int N = in_sizes[0] / 64;
    if (N > NMAX) N = NMAX;
    int E = in_sizes[17] / 2;
    if (E > EMAX) E = EMAX;

    int nb_node = (N + 127) / 128;
    int nb_warp = (N * 32 + 255) / 256;
    int G = (N + 255) / 256;
    int nbE = (E + 255) / 256;

    cudaEventRecord(ev_fork, 0);
    cudaStreamWaitEvent(s1, ev_fork, 0);
    kvec<<<1, 64, 0, s1>>>(Wgat, asrc, adst);
    k1a<<<nb_node, 256, 0, s1>>>(x, wts, Wmlp, bmlp, Wr, bsage, out, N);
    cudaEventRecord(ev_a, s1);

    kinit<<<G, 256>>>((const int*)eidx, N);
    kconvert<<<nbE, 256>>>(eidx, E);
    kbsum<<<G, 256>>>(N);
    kbscan<<<1, 256>>>(G);
    kapply<<<G, 256>>>(N, E);
    kscatter<<<nbE, 256>>>(E);

    cudaStreamWaitEvent(0, ev_a, 0);
    kprep<<<nbE, 256>>>(E);
    kaggA<<<nb_warp, 256>>>(x, N);

    cudaEventRecord(ev_b, 0);
    cudaStreamWaitEvent(s1, ev_b, 0);
    k1b<<<nb_node, 256, 0, s1>>>(x, wts, Wl, Wgin, bgin, out, N);
    cudaEventRecord(ev_j, s1);

    kaggB<<<nb_warp, 256>>>(N);

    cudaStreamWaitEvent(0, ev_j, 0);
    kf<<<nb_node, 256>>>(x, wts, Wcheb, bcheb, Wgcn, bgcn, Wgat, bgat, out, N);
}